// round 9
// baseline (speedup 1.0000x reference)
#include <cuda_runtime.h>
#include <cuda_fp16.h>
#include <cstdint>

// Fused NonLinearReadoutLayer via mma.sync.m16n8k16 (fp16 in, fp32 accum).
// Round 9: x layout-transform fused into main kernel (warp-local staging,
// coalesced LDG + cvt + STS); weights via cp.async pipeline; no prep_x.

#define DIN     512
#define TILE_M  128
#define THREADS 256

#define PA  136   // halves
#define PB  136
#define PW2 40

#define OFF_A0 0u          // x_s -> ch0 -> ch2
#define OFF_R1 34816u      // w1s[0] -> ch1
#define OFF_R2 69632u      // w1s[1] -> w1v
#define OFF_W2 104448u
#define SMEM_BYTES 114688u

__device__ __align__(16) __half g_w1s[2][128 * PB];
__device__ __align__(16) __half g_w1v[128 * PB];
__device__ __align__(16) __half g_w2[128 * PW2];

// ---------------------------------------------------------------- helpers
__device__ __forceinline__ uint32_t smem_u32(const void* p) {
    uint32_t a;
    asm("{ .reg .u64 t; cvta.to.shared.u64 t, %1; cvt.u32.u64 %0, t; }"
        : "=r"(a) : "l"(p));
    return a;
}
__device__ __forceinline__ uint32_t h2u(__half2 h) {
    return *reinterpret_cast<uint32_t*>(&h);
}
__device__ __forceinline__ float sigf(float x) {
    return __fdividef(1.0f, 1.0f + __expf(-x));
}
#define CP16(d, s) \
    asm volatile("cp.async.cg.shared.global [%0], [%1], 16;" \
                 :: "r"(d), "l"(s))
#define CP_COMMIT() asm volatile("cp.async.commit_group;" ::: "memory")
#define CP_WAIT(n)  asm volatile("cp.async.wait_group %0;" :: "n"(n) : "memory")

__device__ __forceinline__ void cp_bulk(uint32_t dst, const void* src, int n16,
                                        int tid) {
    const char* s = (const char*)src;
    for (int i = tid; i < n16; i += THREADS) CP16(dst + i * 16, s + (long)i * 16);
}

__device__ __forceinline__ void ldsm4(uint32_t* r, uint32_t addr) {
    asm volatile("ldmatrix.sync.aligned.m8n8.x4.shared.b16 {%0,%1,%2,%3}, [%4];"
                 : "=r"(r[0]), "=r"(r[1]), "=r"(r[2]), "=r"(r[3]) : "r"(addr));
}
__device__ __forceinline__ void ldsm4t(uint32_t* r, uint32_t addr) {
    asm volatile("ldmatrix.sync.aligned.m8n8.x4.trans.shared.b16 {%0,%1,%2,%3}, [%4];"
                 : "=r"(r[0]), "=r"(r[1]), "=r"(r[2]), "=r"(r[3]) : "r"(addr));
}
__device__ __forceinline__ void mma16816(float* c, const uint32_t* a, const uint32_t* b) {
    asm volatile(
        "mma.sync.aligned.m16n8k16.row.col.f32.f16.f16.f32 "
        "{%0,%1,%2,%3}, {%4,%5,%6,%7}, {%8,%9}, {%0,%1,%2,%3};"
        : "+f"(c[0]), "+f"(c[1]), "+f"(c[2]), "+f"(c[3])
        : "r"(a[0]), "r"(a[1]), "r"(a[2]), "r"(a[3]), "r"(b[0]), "r"(b[1]));
}
__device__ __forceinline__ void ldsmA(uint32_t* af, uint32_t aAddr) {
    #pragma unroll
    for (int k = 0; k < 8; ++k) ldsm4(af + 4 * k, aAddr + k * 32);
}
__device__ __forceinline__ void gemm_rA4(float (*acc)[4], const uint32_t* af,
                                         uint32_t bAddr, uint32_t pbB) {
    #pragma unroll
    for (int k = 0; k < 8; ++k) {
        #pragma unroll
        for (int g = 0; g < 4; ++g) {
            uint32_t b[4];
            ldsm4t(b, bAddr + k * 16 * pbB + g * 32);
            mma16816(acc[2 * g],     af + 4 * k, b);
            mma16816(acc[2 * g + 1], af + 4 * k, b + 2);
        }
    }
}
__device__ __forceinline__ void gemm_rA1(float (*acc)[4], const uint32_t* af,
                                         uint32_t bAddr, uint32_t pbB) {
    #pragma unroll
    for (int k = 0; k < 8; ++k) {
        uint32_t b[4];
        ldsm4t(b, bAddr + k * 16 * pbB);
        mma16816(acc[0], af + 4 * k, b);
        mma16816(acc[1], af + 4 * k, b + 2);
    }
}

// warp-local: extract channel c of this warp's 16 v-rows into dst (pitch PA)
__device__ __forceinline__ void stage_ch(const float* __restrict__ x, long tile0,
                                         int wid, int lane, int N,
                                         char* dstWarp, int c) {
    #pragma unroll 4
    for (int it = 0; it < 16; ++it) {
        long grow = tile0 + wid * 16 + it;
        bool ok = grow < N;
        const float4* p = (const float4*)(x + grow * DIN + 128 + lane * 12);
        float4 f0 = ok ? p[0] : make_float4(0, 0, 0, 0);
        float4 f1 = ok ? p[1] : make_float4(0, 0, 0, 0);
        float4 f2 = ok ? p[2] : make_float4(0, 0, 0, 0);
        float f[12] = {f0.x, f0.y, f0.z, f0.w, f1.x, f1.y, f1.z, f1.w,
                       f2.x, f2.y, f2.z, f2.w};
        uint2 u;
        u.x = h2u(__floats2half2_rn(f[c],     f[3 + c]));
        u.y = h2u(__floats2half2_rn(f[6 + c], f[9 + c]));
        *(uint2*)(dstWarp + (it * PA + lane * 4) * 2) = u;
    }
}

// ---------------------------------------------------------------- prep (weights only)
__global__ void prep_w(const float* __restrict__ w1s, const float* __restrict__ w1v,
                       const float* __restrict__ w2s, const float* __restrict__ w2v) {
    int idx = blockIdx.x * blockDim.x + threadIdx.x;
    int stride = gridDim.x * blockDim.x;
    for (int i = idx; i < 2 * 128 * 128; i += stride) {
        int h = i >> 14, k = (i >> 7) & 127, n = i & 127;
        g_w1s[h][k * PB + n] = __float2half_rn(w1s[k * 256 + h * 128 + n]);
    }
    for (int i = idx; i < 128 * 128; i += stride)
        g_w1v[(i >> 7) * PB + (i & 127)] = __float2half_rn(w1v[i]);
    for (int i = idx; i < 128 * 16; i += stride) {
        int k = i >> 4, n = i & 15;
        g_w2[k * PW2 + n]      = __float2half_rn(w2s[i]);
        g_w2[k * PW2 + 16 + n] = __float2half_rn(w2v[i]);
    }
}

// ---------------------------------------------------------------- main
__global__ void __launch_bounds__(THREADS, 2)
nlro(const float* __restrict__ x, float* __restrict__ out, int N) {
    extern __shared__ char sm[];
    const uint32_t smb = smem_u32(sm);
    const int tid = threadIdx.x, lane = tid & 31, wid = tid >> 5;
    const int tile = blockIdx.x;
    const long tile0 = (long)tile * TILE_M;
    const float INV = 0.08838834764831845f;

    const int row0 = wid * 16 + (lane >> 2);
    const int cpair = 2 * (lane & 3);
    const int l16 = lane & 15, lhi = lane >> 4;

    const uint32_t aOffA0 = smb + OFF_A0 + ((wid * 16 + l16) * PA + lhi * 8) * 2;
    const uint32_t aOffR1 = aOffA0 + (OFF_R1 - OFF_A0);
    const uint32_t bR1   = smb + OFF_R1 + (l16 * PB + lhi * 8) * 2;
    const uint32_t bR2   = smb + OFF_R2 + (l16 * PB + lhi * 8) * 2;
    const uint32_t bOffS = smb + OFF_W2 + (l16 * PW2 + lhi * 8) * 2;
    const uint32_t bOffV = bOffS + 32;

    char* warpA0 = sm + OFF_A0 + wid * 16 * PA * 2;
    char* warpR1 = sm + OFF_R1 + wid * 16 * PA * 2;

    // ---- weight pipeline: G0=R2(w1s[1]), G1=R1(w1s[0]), G2=W2 ----
    cp_bulk(smb + OFF_R2, &g_w1s[1][0], 2176, tid);
    CP_COMMIT();
    cp_bulk(smb + OFF_R1, &g_w1s[0][0], 2176, tid);
    CP_COMMIT();
    cp_bulk(smb + OFF_W2, g_w2, 640, tid);
    CP_COMMIT();

    // ---- stage x_s warp-locally: one 512B row per iteration, coalesced ----
    #pragma unroll 4
    for (int it = 0; it < 16; ++it) {
        long grow = tile0 + wid * 16 + it;
        bool ok = grow < N;
        const float4* p = (const float4*)(x + grow * DIN);
        float4 v = ok ? p[lane] : make_float4(0, 0, 0, 0);
        uint2 u;
        u.x = h2u(__floats2half2_rn(v.x, v.y));
        u.y = h2u(__floats2half2_rn(v.z, v.w));
        *(uint2*)(warpA0 + (it * PA + lane * 4) * 2) = u;
    }
    __syncwarp();

    CP_WAIT(2);            // G0: R2 (w1s[1]) landed (own chunks)
    __syncthreads();       // b1: R2 visible CTA-wide

    uint32_t af[32];
    ldsmA(af, aOffA0);     // x_s fragments -> regs; A0 warp rows now free
    __syncwarp();
    stage_ch(x, tile0, wid, lane, N, warpA0, 0);   // ch0 -> A0 (hidden under gates/act)

    // ======== gates: sigmoid(h_s[:,128:]) -> registers (uses R2) ========
    uint32_t gfa[16], gfb[16];
    #pragma unroll
    for (int h = 0; h < 2; ++h) {
        float acc[8][4] = {};
        gemm_rA4(acc, af, bR2 + h * 128, PB * 2);
        #pragma unroll
        for (int t = 0; t < 8; ++t) {
            gfa[h * 8 + t] = h2u(__floats2half2_rn(sigf(INV * acc[t][0]),
                                                   sigf(INV * acc[t][1])));
            gfb[h * 8 + t] = h2u(__floats2half2_rn(sigf(INV * acc[t][2]),
                                                   sigf(INV * acc[t][3])));
        }
    }

    CP_WAIT(1);            // G1: R1 (w1s[0]) landed
    __syncthreads();       // b2: R1 visible; R2 released by all warps (gates done)

    cp_bulk(smb + OFF_R2, g_w1v, 2176, tid);       // G3: w1v -> R2
    CP_COMMIT();

    // ======== act: silu(h_s[:,:128]) -> A-fragments (uses R1) ========
    uint32_t afrag[32];
    #pragma unroll
    for (int h = 0; h < 2; ++h) {
        float acc[8][4] = {};
        gemm_rA4(acc, af, bR1 + h * 128, PB * 2);
        #pragma unroll
        for (int t = 0; t < 8; t += 2) {
            int kb = h * 4 + (t >> 1);
            float a0 = INV * acc[t][0],     a1 = INV * acc[t][1];
            float a2 = INV * acc[t][2],     a3 = INV * acc[t][3];
            float a4 = INV * acc[t + 1][0], a5 = INV * acc[t + 1][1];
            float a6 = INV * acc[t + 1][2], a7 = INV * acc[t + 1][3];
            a0 *= sigf(a0); a1 *= sigf(a1); a2 *= sigf(a2); a3 *= sigf(a3);
            a4 *= sigf(a4); a5 *= sigf(a5); a6 *= sigf(a6); a7 *= sigf(a7);
            afrag[4 * kb + 0] = h2u(__floats2half2_rn(a0, a1));
            afrag[4 * kb + 1] = h2u(__floats2half2_rn(a2, a3));
            afrag[4 * kb + 2] = h2u(__floats2half2_rn(a4, a5));
            afrag[4 * kb + 3] = h2u(__floats2half2_rn(a6, a7));
        }
    }

    CP_WAIT(1);            // G2: W2 landed (G3 may still fly)
    __syncthreads();       // b3: W2 visible; R1 released by all warps (act done)

    stage_ch(x, tile0, wid, lane, N, warpR1, 1);   // ch1 -> R1 (hidden under L2-s)

    // ======== L2-s from registers; write out_s (uses W2) ========
    {
        float acc2[2][4] = {};
        gemm_rA1(acc2, afrag, bOffS, PW2 * 2);
        long gr0 = tile0 + row0, gr1 = gr0 + 8;
        if (gr0 < N) {
            *(float2*)&out[gr0 * 64 + cpair]     = make_float2(INV * acc2[0][0], INV * acc2[0][1]);
            *(float2*)&out[gr0 * 64 + cpair + 8] = make_float2(INV * acc2[1][0], INV * acc2[1][1]);
        }
        if (gr1 < N) {
            *(float2*)&out[gr1 * 64 + cpair]     = make_float2(INV * acc2[0][2], INV * acc2[0][3]);
            *(float2*)&out[gr1 * 64 + cpair + 8] = make_float2(INV * acc2[1][2], INV * acc2[1][3]);
        }
    }

    CP_WAIT(0);            // G3: w1v landed
    __syncthreads();       // b4 (last): w1v visible CTA-wide

    // ======== per-channel: G1-v -> gate (regs) -> L2-v (warp-local) ========
    float vout[24];
    #define VOUT(r, g, k, c) ((((r) * 2 + (g)) * 2 + (k)) * 3 + (c))
    #pragma unroll
    for (int c = 0; c < 3; ++c) {
        __syncwarp();
        ldsmA(af, (c == 1) ? aOffR1 : aOffA0);
        __syncwarp();
        if (c == 0)                                    // ch2 -> A0, hidden under ch0 GEMM
            stage_ch(x, tile0, wid, lane, N, warpA0, 2);

        #pragma unroll
        for (int h = 0; h < 2; ++h) {
            float acc[8][4] = {};
            gemm_rA4(acc, af, bR2 + h * 128, PB * 2);
            #pragma unroll
            for (int t = 0; t < 8; t += 2) {
                int kb = h * 4 + (t >> 1);
                float2 g00 = __half22float2(*(__half2*)&gfa[h * 8 + t]);
                float2 g01 = __half22float2(*(__half2*)&gfb[h * 8 + t]);
                float2 g10 = __half22float2(*(__half2*)&gfa[h * 8 + t + 1]);
                float2 g11 = __half22float2(*(__half2*)&gfb[h * 8 + t + 1]);
                float a0 = INV * acc[t][0] * g00.x,     a1 = INV * acc[t][1] * g00.y;
                float a2 = INV * acc[t][2] * g01.x,     a3 = INV * acc[t][3] * g01.y;
                float a4 = INV * acc[t + 1][0] * g10.x, a5 = INV * acc[t + 1][1] * g10.y;
                float a6 = INV * acc[t + 1][2] * g11.x, a7 = INV * acc[t + 1][3] * g11.y;
                afrag[4 * kb + 0] = h2u(__floats2half2_rn(a0, a1));
                afrag[4 * kb + 1] = h2u(__floats2half2_rn(a2, a3));
                afrag[4 * kb + 2] = h2u(__floats2half2_rn(a4, a5));
                afrag[4 * kb + 3] = h2u(__floats2half2_rn(a6, a7));
            }
        }
        {
            float acc2[2][4] = {};
            gemm_rA1(acc2, afrag, bOffV, PW2 * 2);
            vout[VOUT(0, 0, 0, c)] = INV * acc2[0][0];
            vout[VOUT(0, 0, 1, c)] = INV * acc2[0][1];
            vout[VOUT(1, 0, 0, c)] = INV * acc2[0][2];
            vout[VOUT(1, 0, 1, c)] = INV * acc2[0][3];
            vout[VOUT(0, 1, 0, c)] = INV * acc2[1][0];
            vout[VOUT(0, 1, 1, c)] = INV * acc2[1][1];
            vout[VOUT(1, 1, 0, c)] = INV * acc2[1][2];
            vout[VOUT(1, 1, 1, c)] = INV * acc2[1][3];
        }
    }

    // ======== write out_v ========
    #pragma unroll
    for (int r = 0; r < 2; ++r) {
        long gr = tile0 + row0 + r * 8;
        if (gr < N) {
            float* op = out + gr * 64 + 16;
            #pragma unroll
            for (int g = 0; g < 2; ++g) {
                int kb = cpair + 8 * g;
                float* q = op + kb * 3;
                *(float2*)(q + 0) = make_float2(vout[VOUT(r, g, 0, 0)], vout[VOUT(r, g, 0, 1)]);
                *(float2*)(q + 2) = make_float2(vout[VOUT(r, g, 0, 2)], vout[VOUT(r, g, 1, 0)]);
                *(float2*)(q + 4) = make_float2(vout[VOUT(r, g, 1, 1)], vout[VOUT(r, g, 1, 2)]);
            }
        }
    }
    #undef VOUT
}

// ---------------------------------------------------------------- launch
extern "C" void kernel_launch(void* const* d_in, const int* in_sizes, int n_in,
                              void* d_out, int out_size) {
    const float* x   = (const float*)d_in[0];
    const float* w1s = (const float*)d_in[1];
    const float* w1v = (const float*)d_in[2];
    const float* w2s = (const float*)d_in[3];
    const float* w2v = (const float*)d_in[4];
    float* out = (float*)d_out;

    const int N = in_sizes[0] / DIN;
    const int tiles = (N + TILE_M - 1) / TILE_M;

    prep_w<<<64, 256>>>(w1s, w1v, w2s, w2v);

    cudaFuncSetAttribute(nlro, cudaFuncAttributeMaxDynamicSharedMemorySize,
                         SMEM_BYTES);
    nlro<<<tiles, THREADS, SMEM_BYTES>>>(x, out, N);
}

// round 10
// speedup vs baseline: 1.1584x; 1.1584x over previous
#include <cuda_runtime.h>
#include <cuda_fp16.h>
#include <cstdint>

// Fused NonLinearReadoutLayer via mma.sync.m16n8k16 (fp16 in, fp32 accum).
// Round 10: R8 structure (prep + cp.async-pipelined main) with prep traffic cut:
// prep converts only the v channels (reads v region only); x_s staged raw in nlro.

#define DIN     512
#define TILE_M  128
#define THREADS 256
#define MAX_TILES 1564

#define PA  136   // halves
#define PB  136
#define PW2 40

#define OFF_A0 0u          // x_s -> ch0 -> ch2
#define OFF_R1 34816u      // w1s[0] -> ch1
#define OFF_R2 69632u      // w1s[1] -> w1v
#define OFF_W2 104448u
#define SMEM_BYTES 114688u

__device__ __align__(16) __half g_w1s[2][128 * PB];
__device__ __align__(16) __half g_w1v[128 * PB];
__device__ __align__(16) __half g_w2[128 * PW2];
__device__ __align__(16) __half g_xv[(long)MAX_TILES * 3 * 128 * PA];

// ---------------------------------------------------------------- helpers
__device__ __forceinline__ uint32_t smem_u32(const void* p) {
    uint32_t a;
    asm("{ .reg .u64 t; cvta.to.shared.u64 t, %1; cvt.u32.u64 %0, t; }"
        : "=r"(a) : "l"(p));
    return a;
}
__device__ __forceinline__ uint32_t h2u(__half2 h) {
    return *reinterpret_cast<uint32_t*>(&h);
}
__device__ __forceinline__ float sigf(float x) {
    return __fdividef(1.0f, 1.0f + __expf(-x));
}
#define CP16(d, s) \
    asm volatile("cp.async.cg.shared.global [%0], [%1], 16;" \
                 :: "r"(d), "l"(s))
#define CP_COMMIT() asm volatile("cp.async.commit_group;" ::: "memory")
#define CP_WAIT(n)  asm volatile("cp.async.wait_group %0;" :: "n"(n) : "memory")

__device__ __forceinline__ void cp_bulk(uint32_t dst, const void* src, int n16,
                                        int tid) {
    const char* s = (const char*)src;
    for (int i = tid; i < n16; i += THREADS) CP16(dst + i * 16, s + (long)i * 16);
}
__device__ __forceinline__ void cp_warp(uint32_t dst, const void* src, int lane) {
    const char* s = (const char*)src;
    #pragma unroll
    for (int i = lane; i < 272; i += 32) CP16(dst + i * 16, s + (long)i * 16);
}

__device__ __forceinline__ void ldsm4(uint32_t* r, uint32_t addr) {
    asm volatile("ldmatrix.sync.aligned.m8n8.x4.shared.b16 {%0,%1,%2,%3}, [%4];"
                 : "=r"(r[0]), "=r"(r[1]), "=r"(r[2]), "=r"(r[3]) : "r"(addr));
}
__device__ __forceinline__ void ldsm4t(uint32_t* r, uint32_t addr) {
    asm volatile("ldmatrix.sync.aligned.m8n8.x4.trans.shared.b16 {%0,%1,%2,%3}, [%4];"
                 : "=r"(r[0]), "=r"(r[1]), "=r"(r[2]), "=r"(r[3]) : "r"(addr));
}
__device__ __forceinline__ void mma16816(float* c, const uint32_t* a, const uint32_t* b) {
    asm volatile(
        "mma.sync.aligned.m16n8k16.row.col.f32.f16.f16.f32 "
        "{%0,%1,%2,%3}, {%4,%5,%6,%7}, {%8,%9}, {%0,%1,%2,%3};"
        : "+f"(c[0]), "+f"(c[1]), "+f"(c[2]), "+f"(c[3])
        : "r"(a[0]), "r"(a[1]), "r"(a[2]), "r"(a[3]), "r"(b[0]), "r"(b[1]));
}
__device__ __forceinline__ void ldsmA(uint32_t* af, uint32_t aAddr) {
    #pragma unroll
    for (int k = 0; k < 8; ++k) ldsm4(af + 4 * k, aAddr + k * 32);
}
__device__ __forceinline__ void gemm_rA4(float (*acc)[4], const uint32_t* af,
                                         uint32_t bAddr, uint32_t pbB) {
    #pragma unroll
    for (int k = 0; k < 8; ++k) {
        #pragma unroll
        for (int g = 0; g < 4; ++g) {
            uint32_t b[4];
            ldsm4t(b, bAddr + k * 16 * pbB + g * 32);
            mma16816(acc[2 * g],     af + 4 * k, b);
            mma16816(acc[2 * g + 1], af + 4 * k, b + 2);
        }
    }
}
__device__ __forceinline__ void gemm_rA1(float (*acc)[4], const uint32_t* af,
                                         uint32_t bAddr, uint32_t pbB) {
    #pragma unroll
    for (int k = 0; k < 8; ++k) {
        uint32_t b[4];
        ldsm4t(b, bAddr + k * 16 * pbB);
        mma16816(acc[0], af + 4 * k, b);
        mma16816(acc[1], af + 4 * k, b + 2);
    }
}

// ---------------------------------------------------------------- prep (v + weights)
__global__ void __launch_bounds__(256)
prep_v(const float* __restrict__ x, int N,
       const float* __restrict__ w1s, const float* __restrict__ w1v,
       const float* __restrict__ w2s, const float* __restrict__ w2v) {
    const int tile = blockIdx.x;
    const int tid = threadIdx.x;
    const long tile0 = (long)tile * TILE_M;

    // weight prep spread over first 64 CTAs
    if (tile < 64) {
        int idx = tile * 256 + tid;
        int stride = 64 * 256;
        for (int i = idx; i < 2 * 128 * 128; i += stride) {
            int h = i >> 14, k = (i >> 7) & 127, n = i & 127;
            g_w1s[h][k * PB + n] = __float2half_rn(w1s[k * 256 + h * 128 + n]);
        }
        for (int i = idx; i < 128 * 128; i += stride)
            g_w1v[(i >> 7) * PB + (i & 127)] = __float2half_rn(w1v[i]);
        for (int i = idx; i < 128 * 16; i += stride) {
            int k = i >> 4, n = i & 15;
            g_w2[k * PW2 + n]      = __float2half_rn(w2s[i]);
            g_w2[k * PW2 + 16 + n] = __float2half_rn(w2v[i]);
        }
    }

    // v part only: 4096 units of 12 floats (reads only bytes 512..2047 of each row)
    #pragma unroll
    for (int it = 0; it < 16; ++it) {
        int u = it * 256 + tid;
        int row = u >> 5, seg = u & 31;
        long grow = tile0 + row;
        bool ok = grow < N;
        const float4* src = (const float4*)(x + grow * DIN + 128 + seg * 12);
        float4 f0 = ok ? src[0] : make_float4(0, 0, 0, 0);
        float4 f1 = ok ? src[1] : make_float4(0, 0, 0, 0);
        float4 f2 = ok ? src[2] : make_float4(0, 0, 0, 0);
        float f[12] = {f0.x, f0.y, f0.z, f0.w, f1.x, f1.y, f1.z, f1.w,
                       f2.x, f2.y, f2.z, f2.w};
        #pragma unroll
        for (int c = 0; c < 3; ++c) {
            uint2 w;
            w.x = h2u(__floats2half2_rn(f[c],     f[3 + c]));
            w.y = h2u(__floats2half2_rn(f[6 + c], f[9 + c]));
            *(uint2*)&g_xv[(((long)tile * 3 + c) * 128 + row) * PA + seg * 4] = w;
        }
    }
}

// ---------------------------------------------------------------- main
__global__ void __launch_bounds__(THREADS, 2)
nlro(const float* __restrict__ x, float* __restrict__ out, int N) {
    extern __shared__ char sm[];
    const uint32_t smb = smem_u32(sm);
    const int tid = threadIdx.x, lane = tid & 31, wid = tid >> 5;
    const int tile = blockIdx.x;
    const long tile0 = (long)tile * TILE_M;
    const float INV = 0.08838834764831845f;

    const int row0 = wid * 16 + (lane >> 2);
    const int cpair = 2 * (lane & 3);
    const int l16 = lane & 15, lhi = lane >> 4;

    const uint32_t aOffA0 = smb + OFF_A0 + ((wid * 16 + l16) * PA + lhi * 8) * 2;
    const uint32_t aOffR1 = aOffA0 + (OFF_R1 - OFF_A0);
    const uint32_t bR1   = smb + OFF_R1 + (l16 * PB + lhi * 8) * 2;
    const uint32_t bR2   = smb + OFF_R2 + (l16 * PB + lhi * 8) * 2;
    const uint32_t bOffS = smb + OFF_W2 + (l16 * PW2 + lhi * 8) * 2;
    const uint32_t bOffV = bOffS + 32;

    const __half* xv0 = &g_xv[((long)tile * 3 + 0) * 128 * PA];
    const __half* xv1 = &g_xv[((long)tile * 3 + 1) * 128 * PA];
    const __half* xv2 = &g_xv[((long)tile * 3 + 2) * 128 * PA];
    const uint32_t warpA0u = smb + OFF_A0 + wid * 16 * PA * 2;
    const uint32_t warpR1u = smb + OFF_R1 + wid * 16 * PA * 2;
    char* warpA0 = sm + OFF_A0 + wid * 16 * PA * 2;
    const long wrows = (long)wid * 16 * PA;

    // ---- weight pipeline: G0=R2(w1s[1]), G1=R1(w1s[0]), G2=W2 ----
    cp_bulk(smb + OFF_R2, &g_w1s[1][0], 2176, tid);
    CP_COMMIT();
    cp_bulk(smb + OFF_R1, &g_w1s[0][0], 2176, tid);
    CP_COMMIT();
    cp_bulk(smb + OFF_W2, g_w2, 640, tid);
    CP_COMMIT();

    // ---- stage x_s raw -> A0 (warp-local, coalesced 512B rows) ----
    #pragma unroll 4
    for (int it = 0; it < 16; ++it) {
        long grow = tile0 + wid * 16 + it;
        bool ok = grow < N;
        const float4* p = (const float4*)(x + grow * DIN);
        float4 v = ok ? p[lane] : make_float4(0, 0, 0, 0);
        uint2 u;
        u.x = h2u(__floats2half2_rn(v.x, v.y));
        u.y = h2u(__floats2half2_rn(v.z, v.w));
        *(uint2*)(warpA0 + (it * PA + lane * 4) * 2) = u;
    }
    __syncwarp();

    CP_WAIT(2);            // G0: R2 (w1s[1]) landed
    __syncthreads();       // b1

    uint32_t af[32];
    ldsmA(af, aOffA0);     // x_s fragments -> regs; A0 warp rows now free
    __syncwarp();
    cp_warp(warpA0u, xv0 + wrows, lane);   // G3: ch0 -> A0 (async, hidden)
    CP_COMMIT();

    // ======== gates: sigmoid(h_s[:,128:]) -> registers (uses R2) ========
    uint32_t gfa[16], gfb[16];
    #pragma unroll
    for (int h = 0; h < 2; ++h) {
        float acc[8][4] = {};
        gemm_rA4(acc, af, bR2 + h * 128, PB * 2);
        #pragma unroll
        for (int t = 0; t < 8; ++t) {
            gfa[h * 8 + t] = h2u(__floats2half2_rn(sigf(INV * acc[t][0]),
                                                   sigf(INV * acc[t][1])));
            gfb[h * 8 + t] = h2u(__floats2half2_rn(sigf(INV * acc[t][2]),
                                                   sigf(INV * acc[t][3])));
        }
    }

    CP_WAIT(2);            // G1: R1 (w1s[0]) landed
    __syncthreads();       // b2: R1 visible; R2 released by all warps

    cp_bulk(smb + OFF_R2, g_w1v, 2176, tid);   // G4: w1v -> R2
    CP_COMMIT();

    // ======== act: silu(h_s[:,:128]) -> A-fragments (uses R1) ========
    uint32_t afrag[32];
    #pragma unroll
    for (int h = 0; h < 2; ++h) {
        float acc[8][4] = {};
        gemm_rA4(acc, af, bR1 + h * 128, PB * 2);
        #pragma unroll
        for (int t = 0; t < 8; t += 2) {
            int kb = h * 4 + (t >> 1);
            float a0 = INV * acc[t][0],     a1 = INV * acc[t][1];
            float a2 = INV * acc[t][2],     a3 = INV * acc[t][3];
            float a4 = INV * acc[t + 1][0], a5 = INV * acc[t + 1][1];
            float a6 = INV * acc[t + 1][2], a7 = INV * acc[t + 1][3];
            a0 *= sigf(a0); a1 *= sigf(a1); a2 *= sigf(a2); a3 *= sigf(a3);
            a4 *= sigf(a4); a5 *= sigf(a5); a6 *= sigf(a6); a7 *= sigf(a7);
            afrag[4 * kb + 0] = h2u(__floats2half2_rn(a0, a1));
            afrag[4 * kb + 1] = h2u(__floats2half2_rn(a2, a3));
            afrag[4 * kb + 2] = h2u(__floats2half2_rn(a4, a5));
            afrag[4 * kb + 3] = h2u(__floats2half2_rn(a6, a7));
        }
    }

    CP_WAIT(2);            // G2: W2 landed (G3, G4 may still fly)
    __syncthreads();       // b3: W2 visible; R1 released by all warps

    cp_warp(warpR1u, xv1 + wrows, lane);   // G5: ch1 -> R1 (async)
    CP_COMMIT();

    // ======== L2-s from registers; write out_s (uses W2) ========
    {
        float acc2[2][4] = {};
        gemm_rA1(acc2, afrag, bOffS, PW2 * 2);
        long gr0 = tile0 + row0, gr1 = gr0 + 8;
        if (gr0 < N) {
            *(float2*)&out[gr0 * 64 + cpair]     = make_float2(INV * acc2[0][0], INV * acc2[0][1]);
            *(float2*)&out[gr0 * 64 + cpair + 8] = make_float2(INV * acc2[1][0], INV * acc2[1][1]);
        }
        if (gr1 < N) {
            *(float2*)&out[gr1 * 64 + cpair]     = make_float2(INV * acc2[0][2], INV * acc2[0][3]);
            *(float2*)&out[gr1 * 64 + cpair + 8] = make_float2(INV * acc2[1][2], INV * acc2[1][3]);
        }
    }

    CP_WAIT(1);            // G3 (ch0) + G4 (w1v) done; G5 may still fly
    __syncthreads();       // b4 (last): w1v visible CTA-wide

    // ======== per-channel: G1-v -> gate (regs) -> L2-v (warp-local) ========
    float vout[24];
    #define VOUT(r, g, k, c) ((((r) * 2 + (g)) * 2 + (k)) * 3 + (c))
    #pragma unroll
    for (int c = 0; c < 3; ++c) {
        if (c == 1) { CP_WAIT(1); __syncwarp(); }   // G5 (ch1) done
        if (c == 2) { CP_WAIT(0); __syncwarp(); }   // G6 (ch2) done
        ldsmA(af, (c == 1) ? aOffR1 : aOffA0);
        if (c == 0) {
            __syncwarp();
            cp_warp(warpA0u, xv2 + wrows, lane);    // G6: ch2 -> A0 (async)
            CP_COMMIT();
        }

        #pragma unroll
        for (int h = 0; h < 2; ++h) {
            float acc[8][4] = {};
            gemm_rA4(acc, af, bR2 + h * 128, PB * 2);
            #pragma unroll
            for (int t = 0; t < 8; t += 2) {
                int kb = h * 4 + (t >> 1);
                float2 g00 = __half22float2(*(__half2*)&gfa[h * 8 + t]);
                float2 g01 = __half22float2(*(__half2*)&gfb[h * 8 + t]);
                float2 g10 = __half22float2(*(__half2*)&gfa[h * 8 + t + 1]);
                float2 g11 = __half22float2(*(__half2*)&gfb[h * 8 + t + 1]);
                float a0 = INV * acc[t][0] * g00.x,     a1 = INV * acc[t][1] * g00.y;
                float a2 = INV * acc[t][2] * g01.x,     a3 = INV * acc[t][3] * g01.y;
                float a4 = INV * acc[t + 1][0] * g10.x, a5 = INV * acc[t + 1][1] * g10.y;
                float a6 = INV * acc[t + 1][2] * g11.x, a7 = INV * acc[t + 1][3] * g11.y;
                afrag[4 * kb + 0] = h2u(__floats2half2_rn(a0, a1));
                afrag[4 * kb + 1] = h2u(__floats2half2_rn(a2, a3));
                afrag[4 * kb + 2] = h2u(__floats2half2_rn(a4, a5));
                afrag[4 * kb + 3] = h2u(__floats2half2_rn(a6, a7));
            }
        }
        {
            float acc2[2][4] = {};
            gemm_rA1(acc2, afrag, bOffV, PW2 * 2);
            vout[VOUT(0, 0, 0, c)] = INV * acc2[0][0];
            vout[VOUT(0, 0, 1, c)] = INV * acc2[0][1];
            vout[VOUT(1, 0, 0, c)] = INV * acc2[0][2];
            vout[VOUT(1, 0, 1, c)] = INV * acc2[0][3];
            vout[VOUT(0, 1, 0, c)] = INV * acc2[1][0];
            vout[VOUT(0, 1, 1, c)] = INV * acc2[1][1];
            vout[VOUT(1, 1, 0, c)] = INV * acc2[1][2];
            vout[VOUT(1, 1, 1, c)] = INV * acc2[1][3];
        }
    }

    // ======== write out_v ========
    #pragma unroll
    for (int r = 0; r < 2; ++r) {
        long gr = tile0 + row0 + r * 8;
        if (gr < N) {
            float* op = out + gr * 64 + 16;
            #pragma unroll
            for (int g = 0; g < 2; ++g) {
                int kb = cpair + 8 * g;
                float* q = op + kb * 3;
                *(float2*)(q + 0) = make_float2(vout[VOUT(r, g, 0, 0)], vout[VOUT(r, g, 0, 1)]);
                *(float2*)(q + 2) = make_float2(vout[VOUT(r, g, 0, 2)], vout[VOUT(r, g, 1, 0)]);
                *(float2*)(q + 4) = make_float2(vout[VOUT(r, g, 1, 1)], vout[VOUT(r, g, 1, 2)]);
            }
        }
    }
    #undef VOUT
}

// ---------------------------------------------------------------- launch
extern "C" void kernel_launch(void* const* d_in, const int* in_sizes, int n_in,
                              void* d_out, int out_size) {
    const float* x   = (const float*)d_in[0];
    const float* w1s = (const float*)d_in[1];
    const float* w1v = (const float*)d_in[2];
    const float* w2s = (const float*)d_in[3];
    const float* w2v = (const float*)d_in[4];
    float* out = (float*)d_out;

    const int N = in_sizes[0] / DIN;
    const int tiles = (N + TILE_M - 1) / TILE_M;

    prep_v<<<tiles, 256>>>(x, N, w1s, w1v, w2s, w2v);

    cudaFuncSetAttribute(nlro, cudaFuncAttributeMaxDynamicSharedMemorySize,
                         SMEM_BYTES);
    nlro<<<tiles, THREADS, SMEM_BYTES>>>(x, out, N);
}

// round 11
// speedup vs baseline: 1.1762x; 1.0153x over previous
#include <cuda_runtime.h>
#include <cuda_fp16.h>
#include <cstdint>

// Fused NonLinearReadoutLayer via mma.sync.m16n8k16 (fp16 in, fp32 accum).
// Round 11: persistent CTAs (1/SM, 512 thr); all weights resident in smem
// (loaded once); warps process independent 16-row strips via atomic
// work-stealing; zero CTA barriers after init.

#define DIN     512
#define THREADS 512
#define NSM     152
#define MAX_TILES 1564

#define PA  136   // halves
#define PB  136
#define PW2 40

// smem layout (bytes)
#define OFF_WG  0u          // w1s[1] (gates B)     34816
#define OFF_WA  34816u      // w1s[0] (act B)       34816
#define OFF_WV  69632u      // w1v                  34816
#define OFF_W2  104448u     // w2s|w2v              10240
#define OFF_AW  114688u     // 16 per-warp A buffers, 4352 B each
#define SMEM_BYTES 184320u

__device__ __align__(16) __half g_w1s[2][128 * PB];
__device__ __align__(16) __half g_w1v[128 * PB];
__device__ __align__(16) __half g_w2[128 * PW2];
__device__ __align__(16) __half g_xv[(long)MAX_TILES * 3 * 128 * PA];
__device__ int g_ctr;

// ---------------------------------------------------------------- helpers
__device__ __forceinline__ uint32_t smem_u32(const void* p) {
    uint32_t a;
    asm("{ .reg .u64 t; cvta.to.shared.u64 t, %1; cvt.u32.u64 %0, t; }"
        : "=r"(a) : "l"(p));
    return a;
}
__device__ __forceinline__ uint32_t h2u(__half2 h) {
    return *reinterpret_cast<uint32_t*>(&h);
}
__device__ __forceinline__ float sigf(float x) {
    return __fdividef(1.0f, 1.0f + __expf(-x));
}
#define CP16(d, s) \
    asm volatile("cp.async.cg.shared.global [%0], [%1], 16;" \
                 :: "r"(d), "l"(s))
#define CP_COMMIT() asm volatile("cp.async.commit_group;" ::: "memory")
#define CP_WAIT(n)  asm volatile("cp.async.wait_group %0;" :: "n"(n) : "memory")

__device__ __forceinline__ void cp_bulk(uint32_t dst, const void* src, int n16,
                                        int tid) {
    const char* s = (const char*)src;
    for (int i = tid; i < n16; i += THREADS) CP16(dst + i * 16, s + (long)i * 16);
}
__device__ __forceinline__ void cp_warp(uint32_t dst, const void* src, int lane) {
    const char* s = (const char*)src;
    #pragma unroll
    for (int i = lane; i < 272; i += 32) CP16(dst + i * 16, s + (long)i * 16);
}

__device__ __forceinline__ void ldsm4(uint32_t* r, uint32_t addr) {
    asm volatile("ldmatrix.sync.aligned.m8n8.x4.shared.b16 {%0,%1,%2,%3}, [%4];"
                 : "=r"(r[0]), "=r"(r[1]), "=r"(r[2]), "=r"(r[3]) : "r"(addr));
}
__device__ __forceinline__ void ldsm4t(uint32_t* r, uint32_t addr) {
    asm volatile("ldmatrix.sync.aligned.m8n8.x4.trans.shared.b16 {%0,%1,%2,%3}, [%4];"
                 : "=r"(r[0]), "=r"(r[1]), "=r"(r[2]), "=r"(r[3]) : "r"(addr));
}
__device__ __forceinline__ void mma16816(float* c, const uint32_t* a, const uint32_t* b) {
    asm volatile(
        "mma.sync.aligned.m16n8k16.row.col.f32.f16.f16.f32 "
        "{%0,%1,%2,%3}, {%4,%5,%6,%7}, {%8,%9}, {%0,%1,%2,%3};"
        : "+f"(c[0]), "+f"(c[1]), "+f"(c[2]), "+f"(c[3])
        : "r"(a[0]), "r"(a[1]), "r"(a[2]), "r"(a[3]), "r"(b[0]), "r"(b[1]));
}
__device__ __forceinline__ void ldsmA(uint32_t* af, uint32_t aAddr) {
    #pragma unroll
    for (int k = 0; k < 8; ++k) ldsm4(af + 4 * k, aAddr + k * 32);
}
__device__ __forceinline__ void gemm_rA4(float (*acc)[4], const uint32_t* af,
                                         uint32_t bAddr, uint32_t pbB) {
    #pragma unroll
    for (int k = 0; k < 8; ++k) {
        #pragma unroll
        for (int g = 0; g < 4; ++g) {
            uint32_t b[4];
            ldsm4t(b, bAddr + k * 16 * pbB + g * 32);
            mma16816(acc[2 * g],     af + 4 * k, b);
            mma16816(acc[2 * g + 1], af + 4 * k, b + 2);
        }
    }
}
__device__ __forceinline__ void gemm_rA1(float (*acc)[4], const uint32_t* af,
                                         uint32_t bAddr, uint32_t pbB) {
    #pragma unroll
    for (int k = 0; k < 8; ++k) {
        uint32_t b[4];
        ldsm4t(b, bAddr + k * 16 * pbB);
        mma16816(acc[0], af + 4 * k, b);
        mma16816(acc[1], af + 4 * k, b + 2);
    }
}

// ---------------------------------------------------------------- prep (v + weights)
__global__ void __launch_bounds__(256)
prep_v(const float* __restrict__ x, int N,
       const float* __restrict__ w1s, const float* __restrict__ w1v,
       const float* __restrict__ w2s, const float* __restrict__ w2v) {
    const int tile = blockIdx.x;
    const int tid = threadIdx.x;
    const long tile0 = (long)tile * 128;

    if (tile == 0 && tid == 0) g_ctr = 0;   // reset work counter for nlro

    if (tile < 64) {
        int idx = tile * 256 + tid;
        int stride = 64 * 256;
        for (int i = idx; i < 2 * 128 * 128; i += stride) {
            int h = i >> 14, k = (i >> 7) & 127, n = i & 127;
            g_w1s[h][k * PB + n] = __float2half_rn(w1s[k * 256 + h * 128 + n]);
        }
        for (int i = idx; i < 128 * 128; i += stride)
            g_w1v[(i >> 7) * PB + (i & 127)] = __float2half_rn(w1v[i]);
        for (int i = idx; i < 128 * 16; i += stride) {
            int k = i >> 4, n = i & 15;
            g_w2[k * PW2 + n]      = __float2half_rn(w2s[i]);
            g_w2[k * PW2 + 16 + n] = __float2half_rn(w2v[i]);
        }
    }

    // v part only: 4096 units of 12 floats
    #pragma unroll
    for (int it = 0; it < 16; ++it) {
        int u = it * 256 + tid;
        int row = u >> 5, seg = u & 31;
        long grow = tile0 + row;
        bool ok = grow < N;
        const float4* src = (const float4*)(x + grow * DIN + 128 + seg * 12);
        float4 f0 = ok ? src[0] : make_float4(0, 0, 0, 0);
        float4 f1 = ok ? src[1] : make_float4(0, 0, 0, 0);
        float4 f2 = ok ? src[2] : make_float4(0, 0, 0, 0);
        float f[12] = {f0.x, f0.y, f0.z, f0.w, f1.x, f1.y, f1.z, f1.w,
                       f2.x, f2.y, f2.z, f2.w};
        #pragma unroll
        for (int c = 0; c < 3; ++c) {
            uint2 w;
            w.x = h2u(__floats2half2_rn(f[c],     f[3 + c]));
            w.y = h2u(__floats2half2_rn(f[6 + c], f[9 + c]));
            *(uint2*)&g_xv[(((long)tile * 3 + c) * 128 + row) * PA + seg * 4] = w;
        }
    }
}

// ---------------------------------------------------------------- main (persistent)
__global__ void __launch_bounds__(THREADS, 1)
nlro(const float* __restrict__ x, float* __restrict__ out, int N) {
    extern __shared__ char sm[];
    const uint32_t smb = smem_u32(sm);
    const int tid = threadIdx.x, lane = tid & 31, wid = tid >> 5;
    const float INV = 0.08838834764831845f;

    const int cpair = 2 * (lane & 3);
    const int l16 = lane & 15, lhi = lane >> 4;

    const uint32_t warpBuf = smb + OFF_AW + wid * 4352u;
    char* warpBufP = sm + OFF_AW + wid * 4352u;
    const uint32_t aOff = warpBuf + (l16 * PA + lhi * 8) * 2;
    const uint32_t bG   = smb + OFF_WG + (l16 * PB + lhi * 8) * 2;
    const uint32_t bA   = smb + OFF_WA + (l16 * PB + lhi * 8) * 2;
    const uint32_t bV   = smb + OFF_WV + (l16 * PB + lhi * 8) * 2;
    const uint32_t bOffS = smb + OFF_W2 + (l16 * PW2 + lhi * 8) * 2;
    const uint32_t bOffV = bOffS + 32;

    // ---- one-time weight residency (only CTA barrier in the kernel) ----
    cp_bulk(smb + OFF_WG, &g_w1s[1][0], 2176, tid);
    cp_bulk(smb + OFF_WA, &g_w1s[0][0], 2176, tid);
    cp_bulk(smb + OFF_WV, g_w1v, 2176, tid);
    cp_bulk(smb + OFF_W2, g_w2, 640, tid);
    CP_COMMIT();
    CP_WAIT(0);
    __syncthreads();

    const int total = (N + 15) >> 4;

    for (;;) {
        int s = 0;
        if (lane == 0) s = atomicAdd(&g_ctr, 1);
        s = __shfl_sync(0xFFFFFFFFu, s, 0);
        if (s >= total) break;

        const long row0g = (long)s * 16;
        const int t = s >> 3, rb = s & 7;
        const __half* xvBase = &g_xv[((long)t * 3) * 128 * PA + (long)rb * 16 * PA];

        // ---- stage x_s (coalesced 512B rows, warp-local) ----
        #pragma unroll 4
        for (int it = 0; it < 16; ++it) {
            long grow = row0g + it;
            bool ok = grow < N;
            const float4* p = (const float4*)(x + grow * DIN);
            float4 v = ok ? p[lane] : make_float4(0, 0, 0, 0);
            uint2 u;
            u.x = h2u(__floats2half2_rn(v.x, v.y));
            u.y = h2u(__floats2half2_rn(v.z, v.w));
            *(uint2*)(warpBufP + (it * PA + lane * 4) * 2) = u;
        }
        __syncwarp();

        uint32_t af[32];
        ldsmA(af, aOff);               // x_s fragments -> regs; buffer free
        __syncwarp();
        cp_warp(warpBuf, xvBase, lane);   // prefetch ch0
        CP_COMMIT();

        // ---- gates: sigmoid(h_s[:,128:]) -> registers ----
        uint32_t gfa[16], gfb[16];
        #pragma unroll
        for (int h = 0; h < 2; ++h) {
            float acc[8][4] = {};
            gemm_rA4(acc, af, bG + h * 128, PB * 2);
            #pragma unroll
            for (int tt = 0; tt < 8; ++tt) {
                gfa[h * 8 + tt] = h2u(__floats2half2_rn(sigf(INV * acc[tt][0]),
                                                        sigf(INV * acc[tt][1])));
                gfb[h * 8 + tt] = h2u(__floats2half2_rn(sigf(INV * acc[tt][2]),
                                                        sigf(INV * acc[tt][3])));
            }
        }

        // ---- act: silu(h_s[:,:128]) -> A-fragments ----
        uint32_t afrag[32];
        #pragma unroll
        for (int h = 0; h < 2; ++h) {
            float acc[8][4] = {};
            gemm_rA4(acc, af, bA + h * 128, PB * 2);
            #pragma unroll
            for (int tt = 0; tt < 8; tt += 2) {
                int kb = h * 4 + (tt >> 1);
                float a0 = INV * acc[tt][0],     a1 = INV * acc[tt][1];
                float a2 = INV * acc[tt][2],     a3 = INV * acc[tt][3];
                float a4 = INV * acc[tt + 1][0], a5 = INV * acc[tt + 1][1];
                float a6 = INV * acc[tt + 1][2], a7 = INV * acc[tt + 1][3];
                a0 *= sigf(a0); a1 *= sigf(a1); a2 *= sigf(a2); a3 *= sigf(a3);
                a4 *= sigf(a4); a5 *= sigf(a5); a6 *= sigf(a6); a7 *= sigf(a7);
                afrag[4 * kb + 0] = h2u(__floats2half2_rn(a0, a1));
                afrag[4 * kb + 1] = h2u(__floats2half2_rn(a2, a3));
                afrag[4 * kb + 2] = h2u(__floats2half2_rn(a4, a5));
                afrag[4 * kb + 3] = h2u(__floats2half2_rn(a6, a7));
            }
        }

        // ---- L2-s; write out_s ----
        {
            float acc2[2][4] = {};
            gemm_rA1(acc2, afrag, bOffS, PW2 * 2);
            long gr0 = row0g + (lane >> 2), gr1 = gr0 + 8;
            if (gr0 < N) {
                *(float2*)&out[gr0 * 64 + cpair]     = make_float2(INV * acc2[0][0], INV * acc2[0][1]);
                *(float2*)&out[gr0 * 64 + cpair + 8] = make_float2(INV * acc2[1][0], INV * acc2[1][1]);
            }
            if (gr1 < N) {
                *(float2*)&out[gr1 * 64 + cpair]     = make_float2(INV * acc2[0][2], INV * acc2[0][3]);
                *(float2*)&out[gr1 * 64 + cpair + 8] = make_float2(INV * acc2[1][2], INV * acc2[1][3]);
            }
        }

        // ---- per-channel: G1-v -> gate (regs) -> L2-v ----
        float vout[24];
        #define VOUT(r, g, k, c) ((((r) * 2 + (g)) * 2 + (k)) * 3 + (c))
        #pragma unroll
        for (int c = 0; c < 3; ++c) {
            CP_WAIT(0);                 // channel c landed
            __syncwarp();
            ldsmA(af, aOff);
            __syncwarp();
            if (c < 2) {                // prefetch channel c+1
                cp_warp(warpBuf, xvBase + (long)(c + 1) * 128 * PA, lane);
                CP_COMMIT();
            }

            #pragma unroll
            for (int h = 0; h < 2; ++h) {
                float acc[8][4] = {};
                gemm_rA4(acc, af, bV + h * 128, PB * 2);
                #pragma unroll
                for (int tt = 0; tt < 8; tt += 2) {
                    int kb = h * 4 + (tt >> 1);
                    float2 g00 = __half22float2(*(__half2*)&gfa[h * 8 + tt]);
                    float2 g01 = __half22float2(*(__half2*)&gfb[h * 8 + tt]);
                    float2 g10 = __half22float2(*(__half2*)&gfa[h * 8 + tt + 1]);
                    float2 g11 = __half22float2(*(__half2*)&gfb[h * 8 + tt + 1]);
                    float a0 = INV * acc[tt][0] * g00.x,     a1 = INV * acc[tt][1] * g00.y;
                    float a2 = INV * acc[tt][2] * g01.x,     a3 = INV * acc[tt][3] * g01.y;
                    float a4 = INV * acc[tt + 1][0] * g10.x, a5 = INV * acc[tt + 1][1] * g10.y;
                    float a6 = INV * acc[tt + 1][2] * g11.x, a7 = INV * acc[tt + 1][3] * g11.y;
                    afrag[4 * kb + 0] = h2u(__floats2half2_rn(a0, a1));
                    afrag[4 * kb + 1] = h2u(__floats2half2_rn(a2, a3));
                    afrag[4 * kb + 2] = h2u(__floats2half2_rn(a4, a5));
                    afrag[4 * kb + 3] = h2u(__floats2half2_rn(a6, a7));
                }
            }
            {
                float acc2[2][4] = {};
                gemm_rA1(acc2, afrag, bOffV, PW2 * 2);
                vout[VOUT(0, 0, 0, c)] = INV * acc2[0][0];
                vout[VOUT(0, 0, 1, c)] = INV * acc2[0][1];
                vout[VOUT(1, 0, 0, c)] = INV * acc2[0][2];
                vout[VOUT(1, 0, 1, c)] = INV * acc2[0][3];
                vout[VOUT(0, 1, 0, c)] = INV * acc2[1][0];
                vout[VOUT(0, 1, 1, c)] = INV * acc2[1][1];
                vout[VOUT(1, 1, 0, c)] = INV * acc2[1][2];
                vout[VOUT(1, 1, 1, c)] = INV * acc2[1][3];
            }
        }

        // ---- write out_v ----
        #pragma unroll
        for (int r = 0; r < 2; ++r) {
            long gr = row0g + (lane >> 2) + r * 8;
            if (gr < N) {
                float* op = out + gr * 64 + 16;
                #pragma unroll
                for (int g = 0; g < 2; ++g) {
                    int kb = cpair + 8 * g;
                    float* q = op + kb * 3;
                    *(float2*)(q + 0) = make_float2(vout[VOUT(r, g, 0, 0)], vout[VOUT(r, g, 0, 1)]);
                    *(float2*)(q + 2) = make_float2(vout[VOUT(r, g, 0, 2)], vout[VOUT(r, g, 1, 0)]);
                    *(float2*)(q + 4) = make_float2(vout[VOUT(r, g, 1, 1)], vout[VOUT(r, g, 1, 2)]);
                }
            }
        }
        #undef VOUT
    }
}

// ---------------------------------------------------------------- launch
extern "C" void kernel_launch(void* const* d_in, const int* in_sizes, int n_in,
                              void* d_out, int out_size) {
    const float* x   = (const float*)d_in[0];
    const float* w1s = (const float*)d_in[1];
    const float* w1v = (const float*)d_in[2];
    const float* w2s = (const float*)d_in[3];
    const float* w2v = (const float*)d_in[4];
    float* out = (float*)d_out;

    const int N = in_sizes[0] / DIN;
    const int tiles = (N + 127) / 128;

    prep_v<<<tiles, 256>>>(x, N, w1s, w1v, w2s, w2v);

    cudaFuncSetAttribute(nlro, cudaFuncAttributeMaxDynamicSharedMemorySize,
                         SMEM_BYTES);
    nlro<<<NSM, THREADS, SMEM_BYTES>>>(x, out, N);
}